// round 2
// baseline (speedup 1.0000x reference)
#include <cuda_runtime.h>
#include <math.h>

// ---------------------------------------------------------------------------
// Problem constants
// ---------------------------------------------------------------------------
#define KD      512          // model dim D
#define KH      8            // heads
#define KDH     64           // head dim
#define KHID    2730         // int(2*512*4*2/3)
#define KB      4            // batch
#define KNS     4096         // spatial tokens
#define KNT     512          // temporal tokens
#define SROWS   (KB*KNS)     // 16384
#define TROWS   (KB*KNT)     // 2048

// ---------------------------------------------------------------------------
// Scratch (static __device__ arrays; no allocation anywhere)
// ---------------------------------------------------------------------------
__device__ float g_ln_s_q [SROWS*KD];
__device__ float g_ln_s_kv[SROWS*KD];
__device__ float g_ln_t_kv[TROWS*KD];
__device__ float g_ln_t_q [TROWS*KD];
__device__ float g_s_q    [SROWS*KD];
__device__ float g_s_kv   [TROWS*2*KD];
__device__ float g_t_q    [TROWS*KD];
__device__ float g_t_kv   [SROWS*2*KD];
__device__ float g_scores [KB*KH*KNS*KNT];   // reused for s- and t-attention
__device__ float g_attn   [SROWS*KD];
__device__ float g_t_attn [TROWS*KD];
__device__ float g_h1     [SROWS*KD];
__device__ float g_t_h1   [TROWS*KD];
__device__ float g_s_ctx  [SROWS*KD];
__device__ float g_t_ctx  [TROWS*KD];
__device__ float g_t_mean [KB*KD];
__device__ float g_hmix   [SROWS*2*KD];
__device__ float g_uv     [(size_t)SROWS*2*KHID];
__device__ float g_gate   [(size_t)SROWS*KHID];

// ---------------------------------------------------------------------------
// Packed f32x2 FMA (sm_103a FFMA2 — PTX-only, see SASS_QUICKREF)
// ---------------------------------------------------------------------------
__device__ __forceinline__ float2 ffma2(float2 a, float2 b, float2 c) {
    unsigned long long ua = *reinterpret_cast<unsigned long long*>(&a);
    unsigned long long ub = *reinterpret_cast<unsigned long long*>(&b);
    unsigned long long uc = *reinterpret_cast<unsigned long long*>(&c);
    unsigned long long ud;
    asm("fma.rn.f32x2 %0, %1, %2, %3;" : "=l"(ud) : "l"(ua), "l"(ub), "l"(uc));
    return *reinterpret_cast<float2*>(&ud);
}

// ---------------------------------------------------------------------------
// Block reductions
// ---------------------------------------------------------------------------
__device__ __forceinline__ float blockReduceSum(float v) {
    __shared__ float sh[33];
    __syncthreads();
    int lane = threadIdx.x & 31, wid = threadIdx.x >> 5;
    #pragma unroll
    for (int o = 16; o; o >>= 1) v += __shfl_xor_sync(0xffffffffu, v, o);
    if (lane == 0) sh[wid] = v;
    __syncthreads();
    if (wid == 0) {
        int nw = (int)(blockDim.x >> 5);
        float r = (lane < nw) ? sh[lane] : 0.f;
        #pragma unroll
        for (int o = 16; o; o >>= 1) r += __shfl_xor_sync(0xffffffffu, r, o);
        if (lane == 0) sh[32] = r;
    }
    __syncthreads();
    return sh[32];
}

__device__ __forceinline__ float blockReduceMax(float v) {
    __shared__ float sh[33];
    __syncthreads();
    int lane = threadIdx.x & 31, wid = threadIdx.x >> 5;
    #pragma unroll
    for (int o = 16; o; o >>= 1) v = fmaxf(v, __shfl_xor_sync(0xffffffffu, v, o));
    if (lane == 0) sh[wid] = v;
    __syncthreads();
    if (wid == 0) {
        int nw = (int)(blockDim.x >> 5);
        float r = (lane < nw) ? sh[lane] : -1e30f;
        #pragma unroll
        for (int o = 16; o; o >>= 1) r = fmaxf(r, __shfl_xor_sync(0xffffffffu, r, o));
        if (lane == 0) sh[32] = r;
    }
    __syncthreads();
    return sh[32];
}

// ---------------------------------------------------------------------------
// LayerNorm: one block (128 threads) per row, Dn in {512, 1024}
// ---------------------------------------------------------------------------
__global__ void __launch_bounds__(128)
ln_kernel(const float* __restrict__ x, const float* __restrict__ g,
          const float* __restrict__ b, float* __restrict__ y, int Dn)
{
    long row = blockIdx.x;
    const float* px = x + row * (long)Dn;
    float* py = y + row * (long)Dn;
    int tid = threadIdx.x;
    int nv = Dn >> 7;
    float v[8];
    float s = 0.f;
    for (int i = 0; i < nv; i++) { v[i] = px[tid + (i << 7)]; s += v[i]; }
    s = blockReduceSum(s);
    float mean = s / (float)Dn;
    float q = 0.f;
    for (int i = 0; i < nv; i++) { float d = v[i] - mean; q += d * d; }
    q = blockReduceSum(q);
    float inv = rsqrtf(q / (float)Dn + 1e-5f);
    for (int i = 0; i < nv; i++) {
        int c = tid + (i << 7);
        py[c] = (v[i] - mean) * inv * g[c] + b[c];
    }
}

// Mix LN: row of [s_ctx(512) | t_mean(512)], Dn = 1024
__global__ void __launch_bounds__(128)
mix_ln_kernel(const float* __restrict__ s_ctx, const float* __restrict__ t_mean,
              const float* __restrict__ g, const float* __restrict__ b,
              float* __restrict__ h)
{
    int row = blockIdx.x;               // 0..16383
    int bb  = row >> 12;                // /4096
    const float* ps = s_ctx + (long)row * KD;
    const float* pm = t_mean + (long)bb * KD;
    float* py = h + (long)row * (2 * KD);
    int tid = threadIdx.x;
    float v[8];
    float s = 0.f;
    #pragma unroll
    for (int i = 0; i < 8; i++) {
        int c = tid + (i << 7);
        v[i] = (c < KD) ? ps[c] : pm[c - KD];
        s += v[i];
    }
    s = blockReduceSum(s);
    float mean = s / 1024.f;
    float q = 0.f;
    #pragma unroll
    for (int i = 0; i < 8; i++) { float d = v[i] - mean; q += d * d; }
    q = blockReduceSum(q);
    float inv = rsqrtf(q / 1024.f + 1e-5f);
    #pragma unroll
    for (int i = 0; i < 8; i++) {
        int c = tid + (i << 7);
        py[c] = (v[i] - mean) * inv * g[c] + b[c];
    }
}

// ---------------------------------------------------------------------------
// Row softmax (in place). cols multiple of 256 (512 or 4096). 256 threads.
// ---------------------------------------------------------------------------
__global__ void __launch_bounds__(256)
softmax_kernel(float* __restrict__ S, int cols)
{
    long row = blockIdx.x;
    float* p = S + row * (long)cols;
    int tid = threadIdx.x;
    int nv = cols >> 8;
    float v[16];
    float mx = -1e30f;
    for (int i = 0; i < nv; i++) { v[i] = p[tid + (i << 8)]; mx = fmaxf(mx, v[i]); }
    mx = blockReduceMax(mx);
    float s = 0.f;
    for (int i = 0; i < nv; i++) { v[i] = expf(v[i] - mx); s += v[i]; }
    s = blockReduceSum(s);
    float inv = 1.f / s;
    for (int i = 0; i < nv; i++) p[tid + (i << 8)] = v[i] * inv;
}

// ---------------------------------------------------------------------------
// t_mean: out[b][d] = mean over 512 tokens of t_ctx
// ---------------------------------------------------------------------------
__global__ void tmean_kernel(const float* __restrict__ t_ctx, float* __restrict__ out)
{
    int idx = blockIdx.x * blockDim.x + threadIdx.x;
    if (idx >= KB * KD) return;
    int bb = idx >> 9, dd = idx & 511;
    const float* p = t_ctx + (long)bb * KNT * KD + dd;
    float s = 0.f;
    for (int t = 0; t < KNT; t++) s += p[t * KD];
    out[idx] = s * (1.f / (float)KNT);
}

// ---------------------------------------------------------------------------
// SiLU gate: g = silu(u) * v,  u = uv[:, :HID], v = uv[:, HID:]
// ---------------------------------------------------------------------------
__global__ void gate_kernel(const float* __restrict__ uv, float* __restrict__ gout)
{
    long idx = (long)blockIdx.x * blockDim.x + threadIdx.x;
    const long total = (long)SROWS * KHID;
    if (idx >= total) return;
    long rowc = idx / KHID;
    int  col  = (int)(idx - rowc * KHID);
    float u  = uv[rowc * (2 * KHID) + col];
    float vv = uv[rowc * (2 * KHID) + KHID + col];
    gout[idx] = (u / (1.f + expf(-u))) * vv;
}

// ---------------------------------------------------------------------------
// GEMM NT: C[m,n] = alpha * sum_k A[m,k] * B[n,k]  (+ bias[n]) (+ Res[m,n])
// 128x128x8 tile, 256 threads, 8x8 per thread via f32x2.
// Batched over blockIdx.z with (b,h)-style offsets: z -> (z/Hn, z%Hn).
// ---------------------------------------------------------------------------
__global__ void __launch_bounds__(256)
gemm_nt(const float* __restrict__ A, const float* __restrict__ B,
        const float* __restrict__ bias, const float* __restrict__ Res,
        float* __restrict__ C,
        int M, int N, int K, int lda, int ldb, int ldc,
        int Hn, long sAb, long sAh, long sBb, long sBh, long sCb, long sCh,
        float alpha)
{
    int z = blockIdx.z;
    int zb = z / Hn, zh = z % Hn;
    A += zb * sAb + zh * sAh;
    B += zb * sBb + zh * sBh;
    C += zb * sCb + zh * sCh;
    if (Res) Res += zb * sCb + zh * sCh;

    __shared__ float As[8][128];
    __shared__ float Bs[8][128];

    int tid = threadIdx.x;
    int tx = tid & 15;      // N direction (8 cols each)
    int ty = tid >> 4;      // M direction (8 rows each)
    int row0 = blockIdx.y * 128;
    int col0 = blockIdx.x * 128;

    float2 acc[8][4];
    #pragma unroll
    for (int i = 0; i < 8; i++)
        #pragma unroll
        for (int j = 0; j < 4; j++) acc[i][j] = make_float2(0.f, 0.f);

    int lrow = tid >> 1;            // 0..127
    int lcol = (tid & 1) * 4;       // 0 or 4
    bool a4 = ((lda & 3) == 0);
    bool b4 = ((ldb & 3) == 0);

    for (int k0 = 0; k0 < K; k0 += 8) {
        // ---- A tile (transposed into As[k][m]) ----
        {
            float vx = 0.f, vy = 0.f, vz = 0.f, vw = 0.f;
            int gr = row0 + lrow;
            int kbase = k0 + lcol;
            if (gr < M) {
                if (a4 && kbase + 3 < K) {
                    float4 v = *reinterpret_cast<const float4*>(A + (long)gr * lda + kbase);
                    vx = v.x; vy = v.y; vz = v.z; vw = v.w;
                } else {
                    const float* pa = A + (long)gr * lda;
                    if (kbase + 0 < K) vx = pa[kbase + 0];
                    if (kbase + 1 < K) vy = pa[kbase + 1];
                    if (kbase + 2 < K) vz = pa[kbase + 2];
                    if (kbase + 3 < K) vw = pa[kbase + 3];
                }
            }
            As[lcol + 0][lrow] = vx; As[lcol + 1][lrow] = vy;
            As[lcol + 2][lrow] = vz; As[lcol + 3][lrow] = vw;
        }
        // ---- B tile (transposed into Bs[k][n]) ----
        {
            float vx = 0.f, vy = 0.f, vz = 0.f, vw = 0.f;
            int gn = col0 + lrow;
            int kbase = k0 + lcol;
            if (gn < N) {
                if (b4 && kbase + 3 < K) {
                    float4 v = *reinterpret_cast<const float4*>(B + (long)gn * ldb + kbase);
                    vx = v.x; vy = v.y; vz = v.z; vw = v.w;
                } else {
                    const float* pb = B + (long)gn * ldb;
                    if (kbase + 0 < K) vx = pb[kbase + 0];
                    if (kbase + 1 < K) vy = pb[kbase + 1];
                    if (kbase + 2 < K) vz = pb[kbase + 2];
                    if (kbase + 3 < K) vw = pb[kbase + 3];
                }
            }
            Bs[lcol + 0][lrow] = vx; Bs[lcol + 1][lrow] = vy;
            Bs[lcol + 2][lrow] = vz; Bs[lcol + 3][lrow] = vw;
        }
        __syncthreads();

        #pragma unroll
        for (int kk = 0; kk < 8; kk++) {
            float4 a0 = *reinterpret_cast<const float4*>(&As[kk][ty * 8]);
            float4 a1 = *reinterpret_cast<const float4*>(&As[kk][ty * 8 + 4]);
            float4 b0 = *reinterpret_cast<const float4*>(&Bs[kk][tx * 8]);
            float4 b1 = *reinterpret_cast<const float4*>(&Bs[kk][tx * 8 + 4]);
            float av[8] = {a0.x, a0.y, a0.z, a0.w, a1.x, a1.y, a1.z, a1.w};
            float2 bv[4] = {make_float2(b0.x, b0.y), make_float2(b0.z, b0.w),
                            make_float2(b1.x, b1.y), make_float2(b1.z, b1.w)};
            #pragma unroll
            for (int i = 0; i < 8; i++) {
                float2 ai = make_float2(av[i], av[i]);
                #pragma unroll
                for (int j = 0; j < 4; j++) acc[i][j] = ffma2(ai, bv[j], acc[i][j]);
            }
        }
        __syncthreads();
    }

    // ---- epilogue ----
    #pragma unroll
    for (int i = 0; i < 8; i++) {
        int gm = row0 + ty * 8 + i;
        if (gm >= M) continue;
        #pragma unroll
        for (int j = 0; j < 4; j++) {
            int gn0 = col0 + tx * 8 + j * 2;
            float vals[2] = {acc[i][j].x, acc[i][j].y};
            #pragma unroll
            for (int l = 0; l < 2; l++) {
                int n = gn0 + l;
                if (n < N) {
                    float v = vals[l] * alpha;
                    if (bias) v += bias[n];
                    if (Res)  v += Res[(long)gm * ldc + n];
                    C[(long)gm * ldc + n] = v;
                }
            }
        }
    }
}

// ---------------------------------------------------------------------------
// GEMM NN: C[m,n] = sum_k A[m,k] * B[k,n]   (attn @ V). 128x64x8 tile.
// ---------------------------------------------------------------------------
__global__ void __launch_bounds__(256)
gemm_nn(const float* __restrict__ A, const float* __restrict__ B,
        float* __restrict__ C,
        int M, int N, int K, int lda, int ldb, int ldc,
        int Hn, long sAb, long sAh, long sBb, long sBh, long sCb, long sCh)
{
    int z = blockIdx.z;
    int zb = z / Hn, zh = z % Hn;
    A += zb * sAb + zh * sAh;
    B += zb * sBb + zh * sBh;
    C += zb * sCb + zh * sCh;

    __shared__ float As[8][128];
    __shared__ float Bs[8][64];

    int tid = threadIdx.x;
    int tx = tid & 15;      // N direction, 4 cols each
    int ty = tid >> 4;      // M direction, 8 rows each
    int row0 = blockIdx.y * 128;
    int col0 = blockIdx.x * 64;

    float2 acc[8][2];
    #pragma unroll
    for (int i = 0; i < 8; i++) { acc[i][0] = make_float2(0.f, 0.f); acc[i][1] = make_float2(0.f, 0.f); }

    int lrow = tid >> 1;
    int lcol = (tid & 1) * 4;
    int brow = tid >> 5;            // 0..7 (k)
    int bcol = (tid & 31) * 2;      // 0..62 (n)

    for (int k0 = 0; k0 < K; k0 += 8) {
        // A tile
        {
            float vx = 0.f, vy = 0.f, vz = 0.f, vw = 0.f;
            int gr = row0 + lrow;
            int kbase = k0 + lcol;
            if (gr < M && kbase + 3 < K) {
                float4 v = *reinterpret_cast<const float4*>(A + (long)gr * lda + kbase);
                vx = v.x; vy = v.y; vz = v.z; vw = v.w;
            } else if (gr < M) {
                const float* pa = A + (long)gr * lda;
                if (kbase + 0 < K) vx = pa[kbase + 0];
                if (kbase + 1 < K) vy = pa[kbase + 1];
                if (kbase + 2 < K) vz = pa[kbase + 2];
                if (kbase + 3 < K) vw = pa[kbase + 3];
            }
            As[lcol + 0][lrow] = vx; As[lcol + 1][lrow] = vy;
            As[lcol + 2][lrow] = vz; As[lcol + 3][lrow] = vw;
        }
        // B tile (natural layout)
        {
            float2 bv = make_float2(0.f, 0.f);
            int gk = k0 + brow;
            int gn = col0 + bcol;
            if (gk < K && gn + 1 < N)
                bv = *reinterpret_cast<const float2*>(B + (long)gk * ldb + gn);
            *reinterpret_cast<float2*>(&Bs[brow][bcol]) = bv;
        }
        __syncthreads();

        #pragma unroll
        for (int kk = 0; kk < 8; kk++) {
            float4 a0 = *reinterpret_cast<const float4*>(&As[kk][ty * 8]);
            float4 a1 = *reinterpret_cast<const float4*>(&As[kk][ty * 8 + 4]);
            float4 bq = *reinterpret_cast<const float4*>(&Bs[kk][tx * 4]);
            float av[8] = {a0.x, a0.y, a0.z, a0.w, a1.x, a1.y, a1.z, a1.w};
            float2 bv0 = make_float2(bq.x, bq.y);
            float2 bv1 = make_float2(bq.z, bq.w);
            #pragma unroll
            for (int i = 0; i < 8; i++) {
                float2 ai = make_float2(av[i], av[i]);
                acc[i][0] = ffma2(ai, bv0, acc[i][0]);
                acc[i][1] = ffma2(ai, bv1, acc[i][1]);
            }
        }
        __syncthreads();
    }

    #pragma unroll
    for (int i = 0; i < 8; i++) {
        int gm = row0 + ty * 8 + i;
        if (gm >= M) continue;
        float* pc = C + (long)gm * ldc + col0 + tx * 4;
        int gn = col0 + tx * 4;
        if (gn + 3 < N) {
            pc[0] = acc[i][0].x; pc[1] = acc[i][0].y;
            pc[2] = acc[i][1].x; pc[3] = acc[i][1].y;
        } else {
            if (gn + 0 < N) pc[0] = acc[i][0].x;
            if (gn + 1 < N) pc[1] = acc[i][0].y;
            if (gn + 2 < N) pc[2] = acc[i][1].x;
            if (gn + 3 < N) pc[3] = acc[i][1].y;
        }
    }
}

// ---------------------------------------------------------------------------
// Host-side launch helpers
// ---------------------------------------------------------------------------
static inline void launch_nt(const float* A, const float* B, const float* bias,
                             const float* res, float* C,
                             int M, int N, int K, int lda, int ldb, int ldc,
                             int Z, int Hn,
                             long sAb, long sAh, long sBb, long sBh,
                             long sCb, long sCh, float alpha)
{
    dim3 grid((N + 127) / 128, (M + 127) / 128, Z);
    gemm_nt<<<grid, 256>>>(A, B, bias, res, C, M, N, K, lda, ldb, ldc,
                           Hn, sAb, sAh, sBb, sBh, sCb, sCh, alpha);
}

static inline void launch_nn(const float* A, const float* B, float* C,
                             int M, int N, int K, int lda, int ldb, int ldc,
                             int Z, int Hn,
                             long sAb, long sAh, long sBb, long sBh,
                             long sCb, long sCh)
{
    dim3 grid((N + 63) / 64, (M + 127) / 128, Z);
    gemm_nn<<<grid, 256>>>(A, B, C, M, N, K, lda, ldb, ldc,
                           Hn, sAb, sAh, sBb, sBh, sCb, sCh);
}

extern "C" void kernel_launch(void* const* d_in, const int* in_sizes, int n_in,
                              void* d_out, int out_size)
{
    (void)in_sizes; (void)n_in; (void)out_size;

    const float* spatial   = (const float*)d_in[0];
    const float* temporal  = (const float*)d_in[1];
    const float* s_ln_q_g  = (const float*)d_in[2];
    const float* s_ln_q_b  = (const float*)d_in[3];
    const float* s_ln_kv_g = (const float*)d_in[4];
    const float* s_ln_kv_b = (const float*)d_in[5];
    const float* s_Wqkv    = (const float*)d_in[6];
    const float* s_bqkv    = (const float*)d_in[7];
    const float* s_Wo      = (const float*)d_in[8];
    const float* s_bo      = (const float*)d_in[9];
    const float* s_Wp      = (const float*)d_in[10];
    const float* s_bp      = (const float*)d_in[11];
    const float* t_ln_q_g  = (const float*)d_in[12];
    const float* t_ln_q_b  = (const float*)d_in[13];
    const float* t_ln_kv_g = (const float*)d_in[14];
    const float* t_ln_kv_b = (const float*)d_in[15];
    const float* t_Wqkv    = (const float*)d_in[16];
    const float* t_bqkv    = (const float*)d_in[17];
    const float* t_Wo      = (const float*)d_in[18];
    const float* t_bo      = (const float*)d_in[19];
    const float* t_Wp      = (const float*)d_in[20];
    const float* t_bp      = (const float*)d_in[21];
    const float* mix_ln_g  = (const float*)d_in[22];
    const float* mix_ln_b  = (const float*)d_in[23];
    const float* mix_Win   = (const float*)d_in[24];
    const float* mix_bin   = (const float*)d_in[25];
    const float* mix_Wout  = (const float*)d_in[26];
    const float* mix_bout  = (const float*)d_in[27];
    float* out = (float*)d_out;

    void* p;
    cudaGetSymbolAddress(&p, g_ln_s_q);  float* ln_s_q  = (float*)p;
    cudaGetSymbolAddress(&p, g_ln_s_kv); float* ln_s_kv = (float*)p;
    cudaGetSymbolAddress(&p, g_ln_t_kv); float* ln_t_kv = (float*)p;
    cudaGetSymbolAddress(&p, g_ln_t_q);  float* ln_t_q  = (float*)p;
    cudaGetSymbolAddress(&p, g_s_q);     float* s_q     = (float*)p;
    cudaGetSymbolAddress(&p, g_s_kv);    float* s_kv    = (float*)p;
    cudaGetSymbolAddress(&p, g_t_q);     float* t_q     = (float*)p;
    cudaGetSymbolAddress(&p, g_t_kv);    float* t_kv    = (float*)p;
    cudaGetSymbolAddress(&p, g_scores);  float* scores  = (float*)p;
    cudaGetSymbolAddress(&p, g_attn);    float* s_attn  = (float*)p;
    cudaGetSymbolAddress(&p, g_t_attn);  float* t_attn  = (float*)p;
    cudaGetSymbolAddress(&p, g_h1);      float* s_h1    = (float*)p;
    cudaGetSymbolAddress(&p, g_t_h1);    float* t_h1    = (float*)p;
    cudaGetSymbolAddress(&p, g_s_ctx);   float* s_ctx   = (float*)p;
    cudaGetSymbolAddress(&p, g_t_ctx);   float* t_ctx   = (float*)p;
    cudaGetSymbolAddress(&p, g_t_mean);  float* t_mean  = (float*)p;
    cudaGetSymbolAddress(&p, g_hmix);    float* hmix    = (float*)p;
    cudaGetSymbolAddress(&p, g_uv);      float* uv      = (float*)p;
    cudaGetSymbolAddress(&p, g_gate);    float* gate    = (float*)p;

    const float sc = 0.125f;  // 1/sqrt(64)

    // ---- LayerNorms ----
    ln_kernel<<<SROWS, 128>>>(spatial,  s_ln_q_g,  s_ln_q_b,  ln_s_q,  KD);
    ln_kernel<<<TROWS, 128>>>(temporal, s_ln_kv_g, s_ln_kv_b, ln_t_kv, KD);
    ln_kernel<<<TROWS, 128>>>(temporal, t_ln_q_g,  t_ln_q_b,  ln_t_q,  KD);
    ln_kernel<<<SROWS, 128>>>(spatial,  t_ln_kv_g, t_ln_kv_b, ln_s_kv, KD);

    // ---- Projections ----
    launch_nt(ln_s_q,  s_Wqkv,           s_bqkv,      nullptr, s_q,
              SROWS, KD, KD, KD, KD, KD, 1, 1, 0,0,0,0,0,0, 1.f);
    launch_nt(ln_t_kv, s_Wqkv + KD*KD,   s_bqkv + KD, nullptr, s_kv,
              TROWS, 2*KD, KD, KD, KD, 2*KD, 1, 1, 0,0,0,0,0,0, 1.f);
    launch_nt(ln_t_q,  t_Wqkv,           t_bqkv,      nullptr, t_q,
              TROWS, KD, KD, KD, KD, KD, 1, 1, 0,0,0,0,0,0, 1.f);
    launch_nt(ln_s_kv, t_Wqkv + KD*KD,   t_bqkv + KD, nullptr, t_kv,
              SROWS, 2*KD, KD, KD, KD, 2*KD, 1, 1, 0,0,0,0,0,0, 1.f);

    // ---- Spatial attention (q: spatial, kv: temporal) ----
    launch_nt(s_q, s_kv, nullptr, nullptr, scores,
              KNS, KNT, KDH, KD, 2*KD, KNT,
              KB*KH, KH,
              (long)KNS*KD, KDH,            // A: b, h offsets
              (long)KNT*2*KD, KDH,          // B(k): b, h offsets
              (long)KH*KNS*KNT, (long)KNS*KNT,
              sc);
    softmax_kernel<<<KB*KH*KNS, 256>>>(scores, KNT);
    launch_nn(scores, s_kv + KD, s_attn,
              KNS, KDH, KNT, KNT, 2*KD, KD,
              KB*KH, KH,
              (long)KH*KNS*KNT, (long)KNS*KNT,
              (long)KNT*2*KD, KDH,
              (long)KNS*KD, KDH);
    launch_nt(s_attn, s_Wo, s_bo, nullptr, s_h1,
              SROWS, KD, KD, KD, KD, KD, 1, 1, 0,0,0,0,0,0, 1.f);
    launch_nt(s_h1, s_Wp, s_bp, spatial, s_ctx,
              SROWS, KD, KD, KD, KD, KD, 1, 1, 0,0,0,0,0,0, 1.f);

    // ---- Temporal attention (q: temporal, kv: spatial) ----
    launch_nt(t_q, t_kv, nullptr, nullptr, scores,
              KNT, KNS, KDH, KD, 2*KD, KNS,
              KB*KH, KH,
              (long)KNT*KD, KDH,
              (long)KNS*2*KD, KDH,
              (long)KH*KNT*KNS, (long)KNT*KNS,
              sc);
    softmax_kernel<<<KB*KH*KNT, 256>>>(scores, KNS);
    launch_nn(scores, t_kv + KD, t_attn,
              KNT, KDH, KNS, KNS, 2*KD, KD,
              KB*KH, KH,
              (long)KH*KNT*KNS, (long)KNT*KNS,
              (long)KNS*2*KD, KDH,
              (long)KNT*KD, KDH);
    launch_nt(t_attn, t_Wo, t_bo, nullptr, t_h1,
              TROWS, KD, KD, KD, KD, KD, 1, 1, 0,0,0,0,0,0, 1.f);
    launch_nt(t_h1, t_Wp, t_bp, temporal, t_ctx,
              TROWS, KD, KD, KD, KD, KD, 1, 1, 0,0,0,0,0,0, 1.f);

    // ---- Mix ----
    tmean_kernel<<<(KB*KD + 127) / 128, 128>>>(t_ctx, t_mean);
    mix_ln_kernel<<<SROWS, 128>>>(s_ctx, t_mean, mix_ln_g, mix_ln_b, hmix);

    launch_nt(hmix, mix_Win, mix_bin, nullptr, uv,
              SROWS, 2*KHID, 2*KD, 2*KD, 2*KD, 2*KHID, 1, 1, 0,0,0,0,0,0, 1.f);

    {
        long total = (long)SROWS * KHID;
        int blocks = (int)((total + 255) / 256);
        gate_kernel<<<blocks, 256>>>(uv, gate);
    }

    launch_nt(gate, mix_Wout, mix_bout, s_ctx, out,
              SROWS, KD, KHID, KHID, KHID, KD, 1, 1, 0,0,0,0,0,0, 1.f);
}